// round 6
// baseline (speedup 1.0000x reference)
#include <cuda_runtime.h>
#include <cstdint>

// SparseAudioModel gather via TMA bulk staging.
//   out[b, s] = sum_e x[b, e, s - time_e],  time_e = idx[b,e]*256, active iff time_e <= s
//
// R6: replace per-lane LDG (plateaued at ~55% DRAM across all schedules) with
// cp.async.bulk (UBLKCP) 2KB G->S copies through an 8-stage mbarrier ring.
// Block = mirror tile pair (k, 63-k): uniform ~66 stages/block, 512 uniform
// blocks = one co-resident wave. Producer warp streams bulk copies; 128
// consumer threads accumulate float4 from smem (predicate uniform per thread
// since times are multiples of 256).

#define S_SAMP  32768
#define N_EV    64
#define STEP    256
#define NBATCH  16
#define TILE    512                    // samples per tile (2 KB)
#define NT      (S_SAMP / TILE)        // 64 tiles
#define PAIRS   (NT / 2)               // 32
#define STAGES  8
#define MAXST   (2 * N_EV)             // 128

__device__ __forceinline__ uint32_t s2u(const void* p) {
    uint32_t a;
    asm("{ .reg .u64 t; cvta.to.shared.u64 t, %1; cvt.u32.u64 %0, t; }"
        : "=r"(a) : "l"(p));
    return a;
}

#define MBAR_INIT(addr, cnt) \
    asm volatile("mbarrier.init.shared.b64 [%0], %1;" :: "r"(addr), "r"(cnt) : "memory")
#define MBAR_EXPECT_TX(addr, bytes) \
    asm volatile("mbarrier.arrive.expect_tx.shared.b64 _, [%0], %1;" :: "r"(addr), "r"(bytes) : "memory")
#define MBAR_ARRIVE(addr) \
    asm volatile("mbarrier.arrive.shared.b64 _, [%0];" :: "r"(addr) : "memory")

#define MBAR_WAIT_PARITY(addr, par) do {                                        \
    uint32_t _m = (addr); uint32_t _p = (par); uint32_t _done;                  \
    asm volatile("{\n\t.reg .pred p;\n\t"                                       \
        "mbarrier.try_wait.parity.acquire.cta.shared::cta.b64 p, [%1], %2;\n\t" \
        "selp.b32 %0, 1, 0, p;\n\t}"                                            \
        : "=r"(_done) : "r"(_m), "r"(_p) : "memory");                           \
    if (!_done) {                                                               \
        asm volatile("{\n\t.reg .pred P1;\n\t"                                  \
            "W_%=:\n\t"                                                         \
            "mbarrier.try_wait.parity.acquire.cta.shared::cta.b64 P1, [%0], %1, 0x989680;\n\t" \
            "@P1 bra.uni D_%=;\n\t"                                             \
            "bra.uni W_%=;\n\t"                                                 \
            "D_%=:\n\t}" :: "r"(_m), "r"(_p) : "memory");                       \
    }                                                                           \
} while (0)

#define BULK_G2S(dst, src, bytes, mbar)                                         \
    asm volatile("cp.async.bulk.shared::cluster.global.mbarrier::complete_tx::bytes " \
                 "[%0], [%1], %2, [%3];"                                        \
                 :: "r"(dst), "l"(src), "r"(bytes), "r"(mbar) : "memory")

__global__ __launch_bounds__(160) void sparse_audio_tma(
    const float* __restrict__ x,      // [B, E, S]
    const int*   __restrict__ idx,    // [B, E]
    float*       __restrict__ out)    // [B, S]
{
    __shared__ alignas(1024) float buf[STAGES][TILE];   // 16 KB ring
    __shared__ uint64_t bar_full[STAGES], bar_empty[STAGES];
    __shared__ int c_info[MAXST];     // (time << 1) | hi_flag, per stage
    __shared__ int p_src[MAXST];      // source float offset within batch slab
    __shared__ int p_meta[MAXST];     // (bytes << 16) | dst_byte_offset
    __shared__ int s_c[4];            // warp counts: lo_w0, lo_w1, hi_w0, hi_w1

    const int t  = threadIdx.x;
    const int kp = blockIdx.x;
    const int b  = blockIdx.y;
    const int loT = kp * TILE;
    const int hiT = (NT - 1 - kp) * TILE;

    if (t == 0) {
        #pragma unroll
        for (int i = 0; i < STAGES; ++i) {
            MBAR_INIT(s2u(&bar_full[i]),  1);
            MBAR_INIT(s2u(&bar_empty[i]), 4);   // 4 consumer warps
        }
    }

    // ---- compact active events per tile (threads 0..63, order-preserving) ----
    int time = 0; unsigned mlo = 0, mhi = 0; bool alo = false, ahi = false;
    if (t < N_EV) {
        time = idx[b * N_EV + t] * STEP;
        alo  = time < loT + TILE;
        ahi  = time < hiT + TILE;
        mlo  = __ballot_sync(0xffffffffu, alo);
        mhi  = __ballot_sync(0xffffffffu, ahi);
        if ((t & 31) == 0) { s_c[t >> 5] = __popc(mlo); s_c[2 + (t >> 5)] = __popc(mhi); }
    }
    __syncthreads();

    const int n_lo  = s_c[0] + s_c[1];
    const int n_tot = n_lo + s_c[2] + s_c[3];

    if (t < N_EV) {
        const int lane = t & 31, w = t >> 5;
        const unsigned lt = (1u << lane) - 1;
        if (alo) {
            int pos = (w ? s_c[0] : 0) + __popc(mlo & lt);
            int off = loT - time, sz = TILE, dst = 0;
            if (off < 0) { dst = -off; sz = TILE + off; off = 0; }
            c_info[pos] = (time << 1);
            p_src[pos]  = t * S_SAMP + off;
            p_meta[pos] = ((sz * 4) << 16) | (dst * 4);
        }
        if (ahi) {
            int pos = n_lo + (w ? s_c[2] : 0) + __popc(mhi & lt);
            int off = hiT - time, sz = TILE, dst = 0;
            if (off < 0) { dst = -off; sz = TILE + off; off = 0; }
            c_info[pos] = (time << 1) | 1;
            p_src[pos]  = t * S_SAMP + off;
            p_meta[pos] = ((sz * 4) << 16) | (dst * 4);
        }
    }
    __syncthreads();

    if (t == 128) {
        // ---- producer: stream bulk copies through the ring ----
        const float* xb = x + (size_t)b * N_EV * S_SAMP;
        int phase = 1;                          // fresh empty barrier passes
        for (int j = 0; j < n_tot; ++j) {
            const int slot = j & (STAGES - 1);
            const int src  = p_src[j];
            const int meta = p_meta[j];
            MBAR_WAIT_PARITY(s2u(&bar_empty[slot]), phase);
            const uint32_t fb = s2u(&bar_full[slot]);
            const int bytes = meta >> 16;
            MBAR_EXPECT_TX(fb, bytes);
            BULK_G2S(s2u(&buf[slot][0]) + (meta & 0xffff), xb + src, bytes, fb);
            if (slot == STAGES - 1) phase ^= 1;
        }
    } else if (t < 128) {
        // ---- consumers: accumulate float4 from staged tiles ----
        float4 al = make_float4(0.f, 0.f, 0.f, 0.f);
        float4 ah = make_float4(0.f, 0.f, 0.f, 0.f);
        int phase = 0;
        for (int j = 0; j < n_tot; ++j) {
            const int slot = j & (STAGES - 1);
            const int info = c_info[j];
            MBAR_WAIT_PARITY(s2u(&bar_full[slot]), phase);
            const int et = info >> 1;
            const int T  = (info & 1) ? hiT : loT;
            if (et <= T + t * 4) {              // uniform over thread's 4 samples
                const float4 v = *reinterpret_cast<const float4*>(&buf[slot][t * 4]);
                if (info & 1) { ah.x += v.x; ah.y += v.y; ah.z += v.z; ah.w += v.w; }
                else          { al.x += v.x; al.y += v.y; al.z += v.z; al.w += v.w; }
            }
            if ((t & 31) == 0) MBAR_ARRIVE(s2u(&bar_empty[slot]));
            if (slot == STAGES - 1) phase ^= 1;
        }
        float* ob = out + (size_t)b * S_SAMP;
        asm("st.global.cs.v4.f32 [%0], {%1, %2, %3, %4};"
            :: "l"(ob + loT + t * 4), "f"(al.x), "f"(al.y), "f"(al.z), "f"(al.w) : "memory");
        asm("st.global.cs.v4.f32 [%0], {%1, %2, %3, %4};"
            :: "l"(ob + hiT + t * 4), "f"(ah.x), "f"(ah.y), "f"(ah.z), "f"(ah.w) : "memory");
    }
}

extern "C" void kernel_launch(void* const* d_in, const int* in_sizes, int n_in,
                              void* d_out, int out_size)
{
    const float* x   = (const float*)d_in[0];   // [16, 64, 32768] float32
    const int*   idx = (const int*)  d_in[1];   // [16, 64] int32
    float*       out = (float*)d_out;           // [16, 1, 32768] float32

    dim3 block(160);                            // 4 consumer warps + 1 producer warp
    dim3 grid(PAIRS, NBATCH);                   // (32, 16) = 512 uniform blocks
    sparse_audio_tma<<<grid, block>>>(x, idx, out);
}